// round 10
// baseline (speedup 1.0000x reference)
#include <cuda_runtime.h>

#define EPS 1e-5f

// ---------------- device scratch ----------------
__device__ float g_Hmk[1024 * 512];    // [b][c:8][l:64]
__device__ float g_Hml[1024 * 256];    // [b][c:8][k:32]
__device__ float g_A1[1024 * 4096];    // layer1 AP post-relu RAW [b][o:64][l:64]
__device__ float g_U1m[1024 * 64];     // mean over k of layer1 UE post-relu RAW [b][c:64]
__device__ float g_stats[512];         // L0: apS,apSS,ueS,ueSS @0,64,128,192; L1 @256..
__device__ float g_TQa[4096];          // 2*Qh1[0]^T [c][o]
__device__ float g_TQu[4096];          // 2*Qh1[2]^T
__device__ float g_TQ2a[4096];         // 2*Qh1[1]^T [c][o]
__device__ float g_TQ2u[4096];         // 2*Qh1[3]^T
__device__ float g_TPa[512];           // 0.1*Ph1[0]^T [c:8][o:64]
__device__ float g_TPu[512];
__device__ float g_TQo[2048];          // 2*Qo[0]^T [c:64][k:32]
__device__ float g_TQo2[2048];         // 2*Qo[1]^T [c:64][k:32]
__device__ float g_TPo[256];           // 0.1*Po[0]^T [c:8][k:32]

static __device__ __forceinline__ float4 ld4(const float* p) { return *reinterpret_cast<const float4*>(p); }
static __device__ __forceinline__ float2 ld2(const float* p) { return *reinterpret_cast<const float2*>(p); }
static __device__ __forceinline__ void st4(float* p, float4 v) { *reinterpret_cast<float4*>(p) = v; }

// ---- Blackwell packed f32x2 math (FFMA2: 2x FMA-pipe throughput, PTX-only) ----
static __device__ __forceinline__ unsigned long long pk2(float lo, float hi) {
    unsigned long long r;
    asm("mov.b64 %0, {%1, %2};" : "=l"(r) : "f"(lo), "f"(hi));
    return r;
}
static __device__ __forceinline__ void upk2(unsigned long long v, float& lo, float& hi) {
    asm("mov.b64 {%0, %1}, %2;" : "=f"(lo), "=f"(hi) : "l"(v));
}
#define FFMA2(d, a, b) asm("fma.rn.f32x2 %0, %1, %2, %0;" : "+l"(d) : "l"(a), "l"(b))

// ---------------- K0 (16 blocks): zero stats + transpose/pre-scale weights ----------------
__global__ void __launch_bounds__(256) k0_prep(const float* __restrict__ Qh,
                                               const float* __restrict__ Ph,
                                               const float* __restrict__ Qo,
                                               const float* __restrict__ Po) {
    int gt = blockIdx.x * 256 + threadIdx.x;   // 0..4095
    if (gt < 512) g_stats[gt] = 0.f;
    {
        int c = gt >> 6, o = gt & 63;
        g_TQa[gt]  = 2.f * Qh[4 * 4096 + o * 64 + c];
        g_TQ2a[gt] = 2.f * Qh[5 * 4096 + o * 64 + c];
        g_TQu[gt]  = 2.f * Qh[6 * 4096 + o * 64 + c];
        g_TQ2u[gt] = 2.f * Qh[7 * 4096 + o * 64 + c];
    }
    if (gt < 512) {
        int c = gt >> 6, o = gt & 63;
        g_TPa[gt] = 0.1f * Ph[1024 + o * 8 + c];
        g_TPu[gt] = 0.1f * Ph[1536 + o * 8 + c];
    }
    if (gt < 2048) {
        int c = gt >> 5, k = gt & 31;
        g_TQo[gt]  = 2.f * Qo[k * 64 + c];
        g_TQo2[gt] = 2.f * Qo[2048 + k * 64 + c];
    }
    if (gt < 256) {
        int c = gt >> 5, k = gt & 31;
        g_TPo[gt] = 0.1f * Po[k * 8 + c];
    }
}

// ---------------- K1: single pass over H -> Hmk/Hml + layer0 stats ----------------
struct SK1 {
    float S[8][64 * 33];    // [c][l*33+k]
    float Hmk[512];
    float Hml[256];
};

__global__ void __launch_bounds__(256, 3) k1_l0(const float* __restrict__ Hr,
                                                const float* __restrict__ Hi,
                                                const float* __restrict__ Ph) {
    extern __shared__ __align__(16) char sraw1[];
    SK1& S = *reinterpret_cast<SK1*>(sraw1);
    int b = blockIdx.x, t = threadIdx.x, w = t >> 5, lane = t & 31;

    const float4* hr4 = reinterpret_cast<const float4*>(Hr) + (size_t)b * 2048;
    const float4* hi4 = reinterpret_cast<const float4*>(Hi) + (size_t)b * 2048;

    float4 r[8], m[8];
#pragma unroll
    for (int i = 0; i < 8; i++) r[i] = hr4[(i * 8 + w) * 32 + lane];
#pragma unroll
    for (int i = 0; i < 8; i++) m[i] = hi4[(i * 8 + w) * 32 + lane];
#pragma unroll
    for (int i = 0; i < 8; i++) {
        int base = (i * 8 + w) * 33 + lane;
        S.S[0][base] = r[i].x; S.S[1][base] = r[i].y;
        S.S[2][base] = r[i].z; S.S[3][base] = r[i].w;
        S.S[4][base] = m[i].x; S.S[5][base] = m[i].y;
        S.S[6][base] = m[i].z; S.S[7][base] = m[i].w;
    }
    __syncthreads();

#pragma unroll
    for (int p = 0; p < 2; p++) {
        int idx = t + p * 256;
        int c = idx >> 6, l = idx & 63;
        float s = 0.f;
#pragma unroll
        for (int k = 0; k < 32; k++) s += S.S[c][l * 33 + k];
        float v = s * (1.f / 32.f);
        S.Hmk[idx] = v;
        g_Hmk[(size_t)b * 512 + idx] = v;
    }
    {
        int c = t >> 5, k = t & 31;
        float s = 0.f;
#pragma unroll
        for (int l = 0; l < 64; l++) s += S.S[c][l * 33 + k];
        float v = s * (1.f / 64.f);
        S.Hml[t] = v;
        g_Hml[(size_t)b * 256 + t] = v;
    }
    __syncthreads();

    int o = t >> 2, q = t & 3;
    float pa[8], pu[8];
#pragma unroll
    for (int c = 0; c < 8; c++) {
        pa[c] = 0.1f * Ph[o * 8 + c];
        pu[c] = 0.1f * Ph[512 + o * 8 + c];
    }
    float ps = 0.f, pss = 0.f;
#pragma unroll
    for (int j = 0; j < 16; j++) {
        int l = q * 16 + j;
        float v = 0.f;
#pragma unroll
        for (int c = 0; c < 8; c++) v += pa[c] * S.Hmk[c * 64 + l];
        v = fmaxf(v, 0.f);
        ps += v; pss += v * v;
    }
    ps += __shfl_xor_sync(0xffffffffu, ps, 1);  ps += __shfl_xor_sync(0xffffffffu, ps, 2);
    pss += __shfl_xor_sync(0xffffffffu, pss, 1); pss += __shfl_xor_sync(0xffffffffu, pss, 2);
    if (q == 0) { atomicAdd(&g_stats[o], ps); atomicAdd(&g_stats[64 + o], pss); }

    float us = 0.f, uss = 0.f;
#pragma unroll
    for (int j = 0; j < 8; j++) {
        int k = q * 8 + j;
        float v = 0.f;
#pragma unroll
        for (int c = 0; c < 8; c++) v += pu[c] * S.Hml[c * 32 + k];
        v = fmaxf(v, 0.f);
        us += v; uss += v * v;
    }
    us += __shfl_xor_sync(0xffffffffu, us, 1);  us += __shfl_xor_sync(0xffffffffu, us, 2);
    uss += __shfl_xor_sync(0xffffffffu, uss, 1); uss += __shfl_xor_sync(0xffffffffu, uss, 2);
    if (q == 0) { atomicAdd(&g_stats[128 + o], us); atomicAdd(&g_stats[192 + o], uss); }
}

// ---------------- K2: recompute layer0 (lazy BN), layer1 GEMMs (packed f32x2), relu, stats ----------------
struct __align__(16) SK2 {
    float AP[4096], UE[2048];
    float Pa[512], Pu[512], P0a[512], P0u[512];
    float Hmk[512], Hml[256];
    float Part[8 * 64];
    float ScA[64], ShA[64], ScU[64], ShU[64];
    float MA[64], MU[64], BA[64], BU[64];
};

__global__ void __launch_bounds__(256) k2_full(const float* __restrict__ Ph,
                                               const float* __restrict__ gamma,
                                               const float* __restrict__ beta) {
    extern __shared__ __align__(16) char sraw[];
    SK2& S = *reinterpret_cast<SK2*>(sraw);
    int b = blockIdx.x, t = threadIdx.x;

    if (t < 64) {
        float m = g_stats[t] * (1.f / 65536.f);
        float v = g_stats[64 + t] * (1.f / 65536.f) - m * m;
        float sc = gamma[t] * rsqrtf(v + EPS);
        S.ScA[t] = sc; S.ShA[t] = beta[t] - m * sc;
        float mu = g_stats[128 + t] * (1.f / 32768.f);
        float vu = g_stats[192 + t] * (1.f / 32768.f) - mu * mu;
        float su = gamma[t] * rsqrtf(vu + EPS);
        S.ScU[t] = su; S.ShU[t] = beta[t] - mu * su;
    }
    for (int i = t; i < 512; i += 256) {
        S.Pa[i] = g_TPa[i]; S.Pu[i] = g_TPu[i];
        S.P0a[i] = 0.1f * Ph[i]; S.P0u[i] = 0.1f * Ph[512 + i];
        S.Hmk[i] = g_Hmk[(size_t)b * 512 + i];
    }
    S.Hml[t] = g_Hml[(size_t)b * 256 + t];
    __syncthreads();

    {
        int l = t & 63, og = t >> 6;
#pragma unroll
        for (int j = 0; j < 16; j++) {
            int o = og * 16 + j;
            float r = 0.f;
#pragma unroll
            for (int c = 0; c < 8; c++) r += S.P0a[o * 8 + c] * S.Hmk[c * 64 + l];
            S.AP[o * 64 + l] = fmaxf(r, 0.f) * S.ScA[o] + S.ShA[o];
        }
        int k = t & 31, og2 = t >> 5;
#pragma unroll
        for (int j = 0; j < 8; j++) {
            int o = og2 * 8 + j;
            float r = 0.f;
#pragma unroll
            for (int c = 0; c < 8; c++) r += S.P0u[o * 8 + c] * S.Hml[c * 32 + k];
            S.UE[o * 32 + k] = fmaxf(r, 0.f) * S.ScU[o] + S.ShU[o];
        }
    }
    __syncthreads();

    {
        int o = t >> 2, q = t & 3;
        float s = 0.f;
#pragma unroll
        for (int j = 0; j < 16; j++) s += S.AP[o * 64 + q * 16 + ((o + j) & 15)];
        s += __shfl_xor_sync(0xffffffffu, s, 1); s += __shfl_xor_sync(0xffffffffu, s, 2);
        if (q == 0) S.MA[o] = s * (1.f / 64.f);
        float su = 0.f;
#pragma unroll
        for (int j = 0; j < 8; j++) su += S.UE[o * 32 + q * 8 + ((o + j) & 7)];
        su += __shfl_xor_sync(0xffffffffu, su, 1); su += __shfl_xor_sync(0xffffffffu, su, 2);
        if (q == 0) S.MU[o] = su * (1.f / 32.f);
    }
    __syncthreads();

    {
        int o = t & 63, g = t >> 6;
        float s = 0.f, su = 0.f;
#pragma unroll
        for (int j = 0; j < 16; j++) {
            int c = g * 16 + j;
            s  += g_TQ2a[c * 64 + o] * S.MU[c];
            su += g_TQ2u[c * 64 + o] * S.MA[c];
        }
        S.Part[g * 64 + o] = s;
        S.Part[256 + g * 64 + o] = su;
    }
    __syncthreads();
    if (t < 64) {
        S.BA[t] = S.Part[t] + S.Part[64 + t] + S.Part[128 + t] + S.Part[192 + t];
        S.BU[t] = S.Part[256 + t] + S.Part[320 + t] + S.Part[384 + t] + S.Part[448 + t];
    }
    __syncthreads();

    // AP GEMM: 4(o) x 4(l) tile, packed f32x2 accumulators (pairs over l)
    int o0 = (t >> 4) * 4, l0 = (t & 15) * 4;
    unsigned long long pA[4][2];
#pragma unroll
    for (int i = 0; i < 4; i++) {
        float bi = S.BA[o0 + i];
        pA[i][0] = pk2(bi, bi);
        pA[i][1] = pA[i][0];
    }
#pragma unroll
    for (int c = 0; c < 8; c++) {
        float4 p = ld4(&S.Pa[c * 64 + o0]);
        float4 h = ld4(&S.Hmk[c * 64 + l0]);
        unsigned long long h01 = pk2(h.x, h.y), h23 = pk2(h.z, h.w);
        unsigned long long q;
        q = pk2(p.x, p.x); FFMA2(pA[0][0], q, h01); FFMA2(pA[0][1], q, h23);
        q = pk2(p.y, p.y); FFMA2(pA[1][0], q, h01); FFMA2(pA[1][1], q, h23);
        q = pk2(p.z, p.z); FFMA2(pA[2][0], q, h01); FFMA2(pA[2][1], q, h23);
        q = pk2(p.w, p.w); FFMA2(pA[3][0], q, h01); FFMA2(pA[3][1], q, h23);
    }
#pragma unroll
    for (int c = 0; c < 64; c++) {
        float4 qv = ld4(&g_TQa[c * 64 + o0]);
        float4 av = ld4(&S.AP[c * 64 + l0]);
        unsigned long long a01 = pk2(av.x, av.y), a23 = pk2(av.z, av.w);
        unsigned long long q;
        q = pk2(qv.x, qv.x); FFMA2(pA[0][0], q, a01); FFMA2(pA[0][1], q, a23);
        q = pk2(qv.y, qv.y); FFMA2(pA[1][0], q, a01); FFMA2(pA[1][1], q, a23);
        q = pk2(qv.z, qv.z); FFMA2(pA[2][0], q, a01); FFMA2(pA[2][1], q, a23);
        q = pk2(qv.w, qv.w); FFMA2(pA[3][0], q, a01); FFMA2(pA[3][1], q, a23);
    }
    float acc[4][4];
#pragma unroll
    for (int i = 0; i < 4; i++) {
        upk2(pA[i][0], acc[i][0], acc[i][1]);
        upk2(pA[i][1], acc[i][2], acc[i][3]);
    }

    // UE GEMM: 2(o) x 4(k) tile, packed f32x2 (pairs over k)
    int ou = (t >> 3) * 2, kq = (t & 7) * 4;
    unsigned long long pU[2][2];
#pragma unroll
    for (int i = 0; i < 2; i++) {
        float bi = S.BU[ou + i];
        pU[i][0] = pk2(bi, bi);
        pU[i][1] = pU[i][0];
    }
#pragma unroll
    for (int c = 0; c < 8; c++) {
        float2 p = ld2(&S.Pu[c * 64 + ou]);
        float4 h = ld4(&S.Hml[c * 32 + kq]);
        unsigned long long h01 = pk2(h.x, h.y), h23 = pk2(h.z, h.w);
        unsigned long long q;
        q = pk2(p.x, p.x); FFMA2(pU[0][0], q, h01); FFMA2(pU[0][1], q, h23);
        q = pk2(p.y, p.y); FFMA2(pU[1][0], q, h01); FFMA2(pU[1][1], q, h23);
    }
#pragma unroll
    for (int c = 0; c < 64; c++) {
        float2 qv = ld2(&g_TQu[c * 64 + ou]);
        float4 uv = ld4(&S.UE[c * 32 + kq]);
        unsigned long long u01 = pk2(uv.x, uv.y), u23 = pk2(uv.z, uv.w);
        unsigned long long q;
        q = pk2(qv.x, qv.x); FFMA2(pU[0][0], q, u01); FFMA2(pU[0][1], q, u23);
        q = pk2(qv.y, qv.y); FFMA2(pU[1][0], q, u01); FFMA2(pU[1][1], q, u23);
    }
    float au[2][4];
#pragma unroll
    for (int i = 0; i < 2; i++) {
        upk2(pU[i][0], au[i][0], au[i][1]);
        upk2(pU[i][1], au[i][2], au[i][3]);
    }

    // epilogue in registers: relu, direct A1 store, shuffle-group stats
    float sA[4], sAS[4];
#pragma unroll
    for (int i = 0; i < 4; i++) {
        float r0 = fmaxf(acc[i][0], 0.f), r1 = fmaxf(acc[i][1], 0.f);
        float r2 = fmaxf(acc[i][2], 0.f), r3 = fmaxf(acc[i][3], 0.f);
        st4(&g_A1[(size_t)b * 4096 + (o0 + i) * 64 + l0], make_float4(r0, r1, r2, r3));
        sA[i] = r0 + r1 + r2 + r3;
        sAS[i] = r0 * r0 + r1 * r1 + r2 * r2 + r3 * r3;
    }
#pragma unroll
    for (int m = 1; m < 16; m <<= 1) {
#pragma unroll
        for (int i = 0; i < 4; i++) {
            sA[i] += __shfl_xor_sync(0xffffffffu, sA[i], m);
            sAS[i] += __shfl_xor_sync(0xffffffffu, sAS[i], m);
        }
    }
    if ((t & 15) == 0) {
#pragma unroll
        for (int i = 0; i < 4; i++) {
            atomicAdd(&g_stats[256 + o0 + i], sA[i]);
            atomicAdd(&g_stats[320 + o0 + i], sAS[i]);
        }
    }

    float sU[2], sUS[2];
#pragma unroll
    for (int i = 0; i < 2; i++) {
        float r0 = fmaxf(au[i][0], 0.f), r1 = fmaxf(au[i][1], 0.f);
        float r2 = fmaxf(au[i][2], 0.f), r3 = fmaxf(au[i][3], 0.f);
        sU[i] = r0 + r1 + r2 + r3;
        sUS[i] = r0 * r0 + r1 * r1 + r2 * r2 + r3 * r3;
    }
#pragma unroll
    for (int m = 1; m < 8; m <<= 1) {
#pragma unroll
        for (int i = 0; i < 2; i++) {
            sU[i] += __shfl_xor_sync(0xffffffffu, sU[i], m);
            sUS[i] += __shfl_xor_sync(0xffffffffu, sUS[i], m);
        }
    }
    if ((t & 7) == 0) {
#pragma unroll
        for (int i = 0; i < 2; i++) {
            atomicAdd(&g_stats[384 + ou + i], sU[i]);
            atomicAdd(&g_stats[448 + ou + i], sUS[i]);
            g_U1m[(size_t)b * 64 + ou + i] = sU[i] * (1.f / 32.f);
        }
    }
}

// ---------------- K3: output layer (packed f32x2) + per-k norm + fused Vhat stream ----------------
__global__ void __launch_bounds__(256) k3_fused(const float* __restrict__ gamma,
                                                const float* __restrict__ beta,
                                                const float* __restrict__ Vh,
                                                float* __restrict__ out) {
    __shared__ float sAP[4096];          // normalized layer1 AP [c][l]
    __shared__ float sPo[256];
    __shared__ float sHmk[512];
    __shared__ float sV[32 * 65];
    __shared__ float sPb[8 * 32];
    __shared__ float sMU[64], sB[32], sFac[32], sScA[64], sShA[64];
    int b = blockIdx.x, t = threadIdx.x;

    float a_raw[16];
#pragma unroll
    for (int j = 0; j < 16; j++) a_raw[j] = g_A1[(size_t)b * 4096 + t + j * 256];

    if (t < 64) {
        float m = g_stats[256 + t] * (1.f / 65536.f);
        float v = g_stats[320 + t] * (1.f / 65536.f) - m * m;
        float sc = gamma[64 + t] * rsqrtf(v + EPS);
        sScA[t] = sc; sShA[t] = beta[64 + t] - m * sc;
        float mu = g_stats[384 + t] * (1.f / 32768.f);
        float vu = g_stats[448 + t] * (1.f / 32768.f) - mu * mu;
        float su = gamma[64 + t] * rsqrtf(vu + EPS);
        float sh = beta[64 + t] - mu * su;
        sMU[t] = g_U1m[(size_t)b * 64 + t] * su + sh;
    }
    sPo[t] = g_TPo[t];
    for (int i = t; i < 512; i += 256) sHmk[i] = g_Hmk[(size_t)b * 512 + i];
    __syncthreads();

#pragma unroll
    for (int j = 0; j < 16; j++) {
        int i = t + j * 256;
        int c = i >> 6;
        sAP[i] = a_raw[j] * sScA[c] + sShA[c];
    }
    {
        int k = t & 31, g = t >> 5;
        float s = 0.f;
#pragma unroll
        for (int j = 0; j < 8; j++) {
            int c = g * 8 + j;
            s += g_TQo2[c * 32 + k] * sMU[c];
        }
        sPb[g * 32 + k] = s;
    }
    __syncthreads();
    if (t < 32) {
        float s = 0.f;
#pragma unroll
        for (int g = 0; g < 8; g++) s += sPb[g * 32 + t];
        sB[t] = s;
    }
    __syncthreads();

    // GEMM 32(k) x 64(l) x 72: thread tile 4(k) x 2(l), packed over the l-pair
    int ko = (t >> 5) * 4, lo = (t & 31) * 2;
    unsigned long long pc[4];
#pragma unroll
    for (int i = 0; i < 4; i++) {
        float bi = sB[ko + i];
        pc[i] = pk2(bi, bi);
    }
#pragma unroll
    for (int c = 0; c < 8; c++) {
        float4 p = ld4(&sPo[c * 32 + ko]);
        unsigned long long h01 = pk2(sHmk[c * 64 + lo], sHmk[c * 64 + lo + 1]);
        unsigned long long q;
        q = pk2(p.x, p.x); FFMA2(pc[0], q, h01);
        q = pk2(p.y, p.y); FFMA2(pc[1], q, h01);
        q = pk2(p.z, p.z); FFMA2(pc[2], q, h01);
        q = pk2(p.w, p.w); FFMA2(pc[3], q, h01);
    }
#pragma unroll
    for (int c = 0; c < 64; c++) {
        float4 qv = ld4(&g_TQo[c * 32 + ko]);
        float2 a = ld2(&sAP[c * 64 + lo]);
        unsigned long long a01 = pk2(a.x, a.y);
        unsigned long long q;
        q = pk2(qv.x, qv.x); FFMA2(pc[0], q, a01);
        q = pk2(qv.y, qv.y); FFMA2(pc[1], q, a01);
        q = pk2(qv.z, qv.z); FFMA2(pc[2], q, a01);
        q = pk2(qv.w, qv.w); FFMA2(pc[3], q, a01);
    }
    float acc[4][2];
#pragma unroll
    for (int i = 0; i < 4; i++) upk2(pc[i], acc[i][0], acc[i][1]);

#pragma unroll
    for (int i = 0; i < 4; i++) {
        sV[(ko + i) * 65 + lo] = acc[i][0];
        sV[(ko + i) * 65 + lo + 1] = acc[i][1];
    }
    __syncthreads();

    {
        int k = t >> 3, j = t & 7;
        float ss = 0.f;
#pragma unroll
        for (int i = 0; i < 8; i++) {
            float x = sV[k * 65 + j * 8 + i];
            ss += x * x;
        }
        ss += __shfl_xor_sync(0xffffffffu, ss, 1);
        ss += __shfl_xor_sync(0xffffffffu, ss, 2);
        ss += __shfl_xor_sync(0xffffffffu, ss, 4);
        if (j == 0) sFac[k] = 8.f * rsqrtf(ss);
    }
    __syncthreads();

    const float4* v4 = reinterpret_cast<const float4*>(Vh) + (size_t)b * 2048;
    float4* o4 = reinterpret_cast<float4*>(out) + (size_t)b * 2048;
    float4 v[8];
#pragma unroll
    for (int j = 0; j < 8; j++) v[j] = v4[t + j * 256];
#pragma unroll
    for (int j = 0; j < 8; j++) {
        int i = t + j * 256;
        int l = i >> 5, k = i & 31;
        float pf = sV[k * 65 + l] * sFac[k];
        v[j].x *= pf; v[j].y *= pf; v[j].z *= pf; v[j].w *= pf;
        o4[i] = v[j];
    }
}

// ---------------- host ----------------
extern "C" void kernel_launch(void* const* d_in, const int* in_sizes, int n_in,
                              void* d_out, int out_size) {
    (void)in_sizes; (void)n_in; (void)out_size;
    const float* Hr = (const float*)d_in[0];
    const float* Hi = (const float*)d_in[1];
    const float* Vh = (const float*)d_in[2];
    const float* Qh = (const float*)d_in[3];
    const float* Ph = (const float*)d_in[4];
    const float* Qo = (const float*)d_in[5];
    const float* Po = (const float*)d_in[6];
    const float* gamma = (const float*)d_in[7];
    const float* beta = (const float*)d_in[8];

    static int attr_done = 0;
    if (!attr_done) {
        cudaFuncSetAttribute(k1_l0, cudaFuncAttributeMaxDynamicSharedMemorySize, (int)sizeof(SK1));
        cudaFuncSetAttribute(k2_full, cudaFuncAttributeMaxDynamicSharedMemorySize, (int)sizeof(SK2));
        attr_done = 1;
    }

    k0_prep<<<16, 256>>>(Qh, Ph, Qo, Po);
    k1_l0<<<1024, 256, sizeof(SK1)>>>(Hr, Hi, Ph);
    k2_full<<<1024, 256, sizeof(SK2)>>>(Ph, gamma, beta);
    k3_fused<<<1024, 256>>>(gamma, beta, Vh, (float*)d_out);
}

// round 11
// speedup vs baseline: 1.0010x; 1.0010x over previous
#include <cuda_runtime.h>

#define EPS 1e-5f

// ---------------- device scratch ----------------
__device__ float g_Hmk[1024 * 512];    // [b][c:8][l:64]
__device__ float g_Hml[1024 * 256];    // [b][c:8][k:32]
__device__ float g_A1[1024 * 4096];    // layer1 AP post-relu RAW [b][o:64][l:64]
__device__ float g_U1m[1024 * 64];     // mean over k of layer1 UE post-relu RAW [b][c:64]
__device__ float g_stats[512];         // L0: apS,apSS,ueS,ueSS @0,64,128,192; L1 @256..
__device__ float g_TQa[4096];          // 2*Qh1[0]^T [c][o]
__device__ float g_TQu[4096];          // 2*Qh1[2]^T
__device__ float g_TQ2a[4096];         // 2*Qh1[1]^T [c][o]
__device__ float g_TQ2u[4096];         // 2*Qh1[3]^T
__device__ float g_TPa[512];           // 0.1*Ph1[0]^T [c:8][o:64]
__device__ float g_TPu[512];
__device__ float g_TQo[2048];          // 2*Qo[0]^T [c:64][k:32]
__device__ float g_TQo2[2048];         // 2*Qo[1]^T [c:64][k:32]
__device__ float g_TPo[256];           // 0.1*Po[0]^T [c:8][k:32]

static __device__ __forceinline__ float4 ld4(const float* p) { return *reinterpret_cast<const float4*>(p); }
static __device__ __forceinline__ float2 ld2(const float* p) { return *reinterpret_cast<const float2*>(p); }
static __device__ __forceinline__ void st4(float* p, float4 v) { *reinterpret_cast<float4*>(p) = v; }

// ---- Blackwell packed f32x2 math (FFMA2: 2x FMA-pipe throughput, PTX-only) ----
static __device__ __forceinline__ unsigned long long pk2(float lo, float hi) {
    unsigned long long r;
    asm("mov.b64 %0, {%1, %2};" : "=l"(r) : "f"(lo), "f"(hi));
    return r;
}
static __device__ __forceinline__ void upk2(unsigned long long v, float& lo, float& hi) {
    asm("mov.b64 {%0, %1}, %2;" : "=f"(lo), "=f"(hi) : "l"(v));
}
#define FFMA2(d, a, b) asm("fma.rn.f32x2 %0, %1, %2, %0;" : "+l"(d) : "l"(a), "l"(b))

// ---------------- K0 (16 blocks): zero stats + transpose/pre-scale weights ----------------
__global__ void __launch_bounds__(256) k0_prep(const float* __restrict__ Qh,
                                               const float* __restrict__ Ph,
                                               const float* __restrict__ Qo,
                                               const float* __restrict__ Po) {
    int gt = blockIdx.x * 256 + threadIdx.x;   // 0..4095
    if (gt < 512) g_stats[gt] = 0.f;
    {
        int c = gt >> 6, o = gt & 63;
        g_TQa[gt]  = 2.f * Qh[4 * 4096 + o * 64 + c];
        g_TQ2a[gt] = 2.f * Qh[5 * 4096 + o * 64 + c];
        g_TQu[gt]  = 2.f * Qh[6 * 4096 + o * 64 + c];
        g_TQ2u[gt] = 2.f * Qh[7 * 4096 + o * 64 + c];
    }
    if (gt < 512) {
        int c = gt >> 6, o = gt & 63;
        g_TPa[gt] = 0.1f * Ph[1024 + o * 8 + c];
        g_TPu[gt] = 0.1f * Ph[1536 + o * 8 + c];
    }
    if (gt < 2048) {
        int c = gt >> 5, k = gt & 31;
        g_TQo[gt]  = 2.f * Qo[k * 64 + c];
        g_TQo2[gt] = 2.f * Qo[2048 + k * 64 + c];
    }
    if (gt < 256) {
        int c = gt >> 5, k = gt & 31;
        g_TPo[gt] = 0.1f * Po[k * 8 + c];
    }
}

// ---------------- K1: single pass over H -> Hmk/Hml + layer0 stats ----------------
struct SK1 {
    float S[8][64 * 33];    // [c][l*33+k]
    float Hmk[512];
    float Hml[256];
};

__global__ void __launch_bounds__(256, 3) k1_l0(const float* __restrict__ Hr,
                                                const float* __restrict__ Hi,
                                                const float* __restrict__ Ph) {
    extern __shared__ __align__(16) char sraw1[];
    SK1& S = *reinterpret_cast<SK1*>(sraw1);
    int b = blockIdx.x, t = threadIdx.x, w = t >> 5, lane = t & 31;

    const float4* hr4 = reinterpret_cast<const float4*>(Hr) + (size_t)b * 2048;
    const float4* hi4 = reinterpret_cast<const float4*>(Hi) + (size_t)b * 2048;

    float4 r[8], m[8];
#pragma unroll
    for (int i = 0; i < 8; i++) r[i] = hr4[(i * 8 + w) * 32 + lane];
#pragma unroll
    for (int i = 0; i < 8; i++) m[i] = hi4[(i * 8 + w) * 32 + lane];
#pragma unroll
    for (int i = 0; i < 8; i++) {
        int base = (i * 8 + w) * 33 + lane;
        S.S[0][base] = r[i].x; S.S[1][base] = r[i].y;
        S.S[2][base] = r[i].z; S.S[3][base] = r[i].w;
        S.S[4][base] = m[i].x; S.S[5][base] = m[i].y;
        S.S[6][base] = m[i].z; S.S[7][base] = m[i].w;
    }
    __syncthreads();

#pragma unroll
    for (int p = 0; p < 2; p++) {
        int idx = t + p * 256;
        int c = idx >> 6, l = idx & 63;
        float s = 0.f;
#pragma unroll
        for (int k = 0; k < 32; k++) s += S.S[c][l * 33 + k];
        float v = s * (1.f / 32.f);
        S.Hmk[idx] = v;
        g_Hmk[(size_t)b * 512 + idx] = v;
    }
    {
        int c = t >> 5, k = t & 31;
        float s = 0.f;
#pragma unroll
        for (int l = 0; l < 64; l++) s += S.S[c][l * 33 + k];
        float v = s * (1.f / 64.f);
        S.Hml[t] = v;
        g_Hml[(size_t)b * 256 + t] = v;
    }
    __syncthreads();

    int o = t >> 2, q = t & 3;
    float pa[8], pu[8];
#pragma unroll
    for (int c = 0; c < 8; c++) {
        pa[c] = 0.1f * Ph[o * 8 + c];
        pu[c] = 0.1f * Ph[512 + o * 8 + c];
    }
    float ps = 0.f, pss = 0.f;
#pragma unroll
    for (int j = 0; j < 16; j++) {
        int l = q * 16 + j;
        float v = 0.f;
#pragma unroll
        for (int c = 0; c < 8; c++) v += pa[c] * S.Hmk[c * 64 + l];
        v = fmaxf(v, 0.f);
        ps += v; pss += v * v;
    }
    ps += __shfl_xor_sync(0xffffffffu, ps, 1);  ps += __shfl_xor_sync(0xffffffffu, ps, 2);
    pss += __shfl_xor_sync(0xffffffffu, pss, 1); pss += __shfl_xor_sync(0xffffffffu, pss, 2);
    if (q == 0) { atomicAdd(&g_stats[o], ps); atomicAdd(&g_stats[64 + o], pss); }

    float us = 0.f, uss = 0.f;
#pragma unroll
    for (int j = 0; j < 8; j++) {
        int k = q * 8 + j;
        float v = 0.f;
#pragma unroll
        for (int c = 0; c < 8; c++) v += pu[c] * S.Hml[c * 32 + k];
        v = fmaxf(v, 0.f);
        us += v; uss += v * v;
    }
    us += __shfl_xor_sync(0xffffffffu, us, 1);  us += __shfl_xor_sync(0xffffffffu, us, 2);
    uss += __shfl_xor_sync(0xffffffffu, uss, 1); uss += __shfl_xor_sync(0xffffffffu, uss, 2);
    if (q == 0) { atomicAdd(&g_stats[128 + o], us); atomicAdd(&g_stats[192 + o], uss); }
}

// ---------------- K2: recompute layer0 (lazy BN), layer1 GEMMs (packed f32x2), relu, stats ----------------
struct __align__(16) SK2 {
    float AP[4096], UE[2048];
    float Pa[512], Pu[512], P0a[512], P0u[512];
    float Hmk[512], Hml[256];
    float Part[8 * 64];
    float ScA[64], ShA[64], ScU[64], ShU[64];
    float MA[64], MU[64], BA[64], BU[64];
};

__global__ void __launch_bounds__(256) k2_full(const float* __restrict__ Ph,
                                               const float* __restrict__ gamma,
                                               const float* __restrict__ beta) {
    extern __shared__ __align__(16) char sraw[];
    SK2& S = *reinterpret_cast<SK2*>(sraw);
    int b = blockIdx.x, t = threadIdx.x;

    if (t < 64) {
        float m = g_stats[t] * (1.f / 65536.f);
        float v = g_stats[64 + t] * (1.f / 65536.f) - m * m;
        float sc = gamma[t] * rsqrtf(v + EPS);
        S.ScA[t] = sc; S.ShA[t] = beta[t] - m * sc;
        float mu = g_stats[128 + t] * (1.f / 32768.f);
        float vu = g_stats[192 + t] * (1.f / 32768.f) - mu * mu;
        float su = gamma[t] * rsqrtf(vu + EPS);
        S.ScU[t] = su; S.ShU[t] = beta[t] - mu * su;
    }
    for (int i = t; i < 512; i += 256) {
        S.Pa[i] = g_TPa[i]; S.Pu[i] = g_TPu[i];
        S.P0a[i] = 0.1f * Ph[i]; S.P0u[i] = 0.1f * Ph[512 + i];
        S.Hmk[i] = g_Hmk[(size_t)b * 512 + i];
    }
    S.Hml[t] = g_Hml[(size_t)b * 256 + t];
    __syncthreads();

    {
        int l = t & 63, og = t >> 6;
#pragma unroll
        for (int j = 0; j < 16; j++) {
            int o = og * 16 + j;
            float r = 0.f;
#pragma unroll
            for (int c = 0; c < 8; c++) r += S.P0a[o * 8 + c] * S.Hmk[c * 64 + l];
            S.AP[o * 64 + l] = fmaxf(r, 0.f) * S.ScA[o] + S.ShA[o];
        }
        int k = t & 31, og2 = t >> 5;
#pragma unroll
        for (int j = 0; j < 8; j++) {
            int o = og2 * 8 + j;
            float r = 0.f;
#pragma unroll
            for (int c = 0; c < 8; c++) r += S.P0u[o * 8 + c] * S.Hml[c * 32 + k];
            S.UE[o * 32 + k] = fmaxf(r, 0.f) * S.ScU[o] + S.ShU[o];
        }
    }
    __syncthreads();

    {
        int o = t >> 2, q = t & 3;
        float s = 0.f;
#pragma unroll
        for (int j = 0; j < 16; j++) s += S.AP[o * 64 + q * 16 + ((o + j) & 15)];
        s += __shfl_xor_sync(0xffffffffu, s, 1); s += __shfl_xor_sync(0xffffffffu, s, 2);
        if (q == 0) S.MA[o] = s * (1.f / 64.f);
        float su = 0.f;
#pragma unroll
        for (int j = 0; j < 8; j++) su += S.UE[o * 32 + q * 8 + ((o + j) & 7)];
        su += __shfl_xor_sync(0xffffffffu, su, 1); su += __shfl_xor_sync(0xffffffffu, su, 2);
        if (q == 0) S.MU[o] = su * (1.f / 32.f);
    }
    __syncthreads();

    {
        int o = t & 63, g = t >> 6;
        float s = 0.f, su = 0.f;
#pragma unroll
        for (int j = 0; j < 16; j++) {
            int c = g * 16 + j;
            s  += g_TQ2a[c * 64 + o] * S.MU[c];
            su += g_TQ2u[c * 64 + o] * S.MA[c];
        }
        S.Part[g * 64 + o] = s;
        S.Part[256 + g * 64 + o] = su;
    }
    __syncthreads();
    if (t < 64) {
        S.BA[t] = S.Part[t] + S.Part[64 + t] + S.Part[128 + t] + S.Part[192 + t];
        S.BU[t] = S.Part[256 + t] + S.Part[320 + t] + S.Part[384 + t] + S.Part[448 + t];
    }
    __syncthreads();

    // AP GEMM: 4(o) x 4(l) tile, packed f32x2 accumulators (pairs over l)
    int o0 = (t >> 4) * 4, l0 = (t & 15) * 4;
    unsigned long long pA[4][2];
#pragma unroll
    for (int i = 0; i < 4; i++) {
        float bi = S.BA[o0 + i];
        pA[i][0] = pk2(bi, bi);
        pA[i][1] = pA[i][0];
    }
#pragma unroll
    for (int c = 0; c < 8; c++) {
        float4 p = ld4(&S.Pa[c * 64 + o0]);
        float4 h = ld4(&S.Hmk[c * 64 + l0]);
        unsigned long long h01 = pk2(h.x, h.y), h23 = pk2(h.z, h.w);
        unsigned long long q;
        q = pk2(p.x, p.x); FFMA2(pA[0][0], q, h01); FFMA2(pA[0][1], q, h23);
        q = pk2(p.y, p.y); FFMA2(pA[1][0], q, h01); FFMA2(pA[1][1], q, h23);
        q = pk2(p.z, p.z); FFMA2(pA[2][0], q, h01); FFMA2(pA[2][1], q, h23);
        q = pk2(p.w, p.w); FFMA2(pA[3][0], q, h01); FFMA2(pA[3][1], q, h23);
    }
#pragma unroll
    for (int c = 0; c < 64; c++) {
        float4 qv = ld4(&g_TQa[c * 64 + o0]);
        float4 av = ld4(&S.AP[c * 64 + l0]);
        unsigned long long a01 = pk2(av.x, av.y), a23 = pk2(av.z, av.w);
        unsigned long long q;
        q = pk2(qv.x, qv.x); FFMA2(pA[0][0], q, a01); FFMA2(pA[0][1], q, a23);
        q = pk2(qv.y, qv.y); FFMA2(pA[1][0], q, a01); FFMA2(pA[1][1], q, a23);
        q = pk2(qv.z, qv.z); FFMA2(pA[2][0], q, a01); FFMA2(pA[2][1], q, a23);
        q = pk2(qv.w, qv.w); FFMA2(pA[3][0], q, a01); FFMA2(pA[3][1], q, a23);
    }
    float acc[4][4];
#pragma unroll
    for (int i = 0; i < 4; i++) {
        upk2(pA[i][0], acc[i][0], acc[i][1]);
        upk2(pA[i][1], acc[i][2], acc[i][3]);
    }

    // UE GEMM: 2(o) x 4(k) tile, packed f32x2 (pairs over k)
    int ou = (t >> 3) * 2, kq = (t & 7) * 4;
    unsigned long long pU[2][2];
#pragma unroll
    for (int i = 0; i < 2; i++) {
        float bi = S.BU[ou + i];
        pU[i][0] = pk2(bi, bi);
        pU[i][1] = pU[i][0];
    }
#pragma unroll
    for (int c = 0; c < 8; c++) {
        float2 p = ld2(&S.Pu[c * 64 + ou]);
        float4 h = ld4(&S.Hml[c * 32 + kq]);
        unsigned long long h01 = pk2(h.x, h.y), h23 = pk2(h.z, h.w);
        unsigned long long q;
        q = pk2(p.x, p.x); FFMA2(pU[0][0], q, h01); FFMA2(pU[0][1], q, h23);
        q = pk2(p.y, p.y); FFMA2(pU[1][0], q, h01); FFMA2(pU[1][1], q, h23);
    }
#pragma unroll
    for (int c = 0; c < 64; c++) {
        float2 qv = ld2(&g_TQu[c * 64 + ou]);
        float4 uv = ld4(&S.UE[c * 32 + kq]);
        unsigned long long u01 = pk2(uv.x, uv.y), u23 = pk2(uv.z, uv.w);
        unsigned long long q;
        q = pk2(qv.x, qv.x); FFMA2(pU[0][0], q, u01); FFMA2(pU[0][1], q, u23);
        q = pk2(qv.y, qv.y); FFMA2(pU[1][0], q, u01); FFMA2(pU[1][1], q, u23);
    }
    float au[2][4];
#pragma unroll
    for (int i = 0; i < 2; i++) {
        upk2(pU[i][0], au[i][0], au[i][1]);
        upk2(pU[i][1], au[i][2], au[i][3]);
    }

    // epilogue in registers: relu, direct A1 store, shuffle-group stats
    float sA[4], sAS[4];
#pragma unroll
    for (int i = 0; i < 4; i++) {
        float r0 = fmaxf(acc[i][0], 0.f), r1 = fmaxf(acc[i][1], 0.f);
        float r2 = fmaxf(acc[i][2], 0.f), r3 = fmaxf(acc[i][3], 0.f);
        st4(&g_A1[(size_t)b * 4096 + (o0 + i) * 64 + l0], make_float4(r0, r1, r2, r3));
        sA[i] = r0 + r1 + r2 + r3;
        sAS[i] = r0 * r0 + r1 * r1 + r2 * r2 + r3 * r3;
    }
#pragma unroll
    for (int m = 1; m < 16; m <<= 1) {
#pragma unroll
        for (int i = 0; i < 4; i++) {
            sA[i] += __shfl_xor_sync(0xffffffffu, sA[i], m);
            sAS[i] += __shfl_xor_sync(0xffffffffu, sAS[i], m);
        }
    }
    if ((t & 15) == 0) {
#pragma unroll
        for (int i = 0; i < 4; i++) {
            atomicAdd(&g_stats[256 + o0 + i], sA[i]);
            atomicAdd(&g_stats[320 + o0 + i], sAS[i]);
        }
    }

    float sU[2], sUS[2];
#pragma unroll
    for (int i = 0; i < 2; i++) {
        float r0 = fmaxf(au[i][0], 0.f), r1 = fmaxf(au[i][1], 0.f);
        float r2 = fmaxf(au[i][2], 0.f), r3 = fmaxf(au[i][3], 0.f);
        sU[i] = r0 + r1 + r2 + r3;
        sUS[i] = r0 * r0 + r1 * r1 + r2 * r2 + r3 * r3;
    }
#pragma unroll
    for (int m = 1; m < 8; m <<= 1) {
#pragma unroll
        for (int i = 0; i < 2; i++) {
            sU[i] += __shfl_xor_sync(0xffffffffu, sU[i], m);
            sUS[i] += __shfl_xor_sync(0xffffffffu, sUS[i], m);
        }
    }
    if ((t & 7) == 0) {
#pragma unroll
        for (int i = 0; i < 2; i++) {
            atomicAdd(&g_stats[384 + ou + i], sU[i]);
            atomicAdd(&g_stats[448 + ou + i], sUS[i]);
            g_U1m[(size_t)b * 64 + ou + i] = sU[i] * (1.f / 32.f);
        }
    }
}

// ---------------- K3: output layer (packed f32x2) + per-k norm + fused Vhat stream ----------------
__global__ void __launch_bounds__(256) k3_fused(const float* __restrict__ gamma,
                                                const float* __restrict__ beta,
                                                const float* __restrict__ Vh,
                                                float* __restrict__ out) {
    __shared__ float sAP[4096];          // normalized layer1 AP [c][l]
    __shared__ float sPo[256];
    __shared__ float sHmk[512];
    __shared__ float sV[32 * 65];
    __shared__ float sPb[8 * 32];
    __shared__ float sMU[64], sB[32], sFac[32], sScA[64], sShA[64];
    int b = blockIdx.x, t = threadIdx.x;

    float a_raw[16];
#pragma unroll
    for (int j = 0; j < 16; j++) a_raw[j] = g_A1[(size_t)b * 4096 + t + j * 256];

    if (t < 64) {
        float m = g_stats[256 + t] * (1.f / 65536.f);
        float v = g_stats[320 + t] * (1.f / 65536.f) - m * m;
        float sc = gamma[64 + t] * rsqrtf(v + EPS);
        sScA[t] = sc; sShA[t] = beta[64 + t] - m * sc;
        float mu = g_stats[384 + t] * (1.f / 32768.f);
        float vu = g_stats[448 + t] * (1.f / 32768.f) - mu * mu;
        float su = gamma[64 + t] * rsqrtf(vu + EPS);
        float sh = beta[64 + t] - mu * su;
        sMU[t] = g_U1m[(size_t)b * 64 + t] * su + sh;
    }
    sPo[t] = g_TPo[t];
    for (int i = t; i < 512; i += 256) sHmk[i] = g_Hmk[(size_t)b * 512 + i];
    __syncthreads();

#pragma unroll
    for (int j = 0; j < 16; j++) {
        int i = t + j * 256;
        int c = i >> 6;
        sAP[i] = a_raw[j] * sScA[c] + sShA[c];
    }
    {
        int k = t & 31, g = t >> 5;
        float s = 0.f;
#pragma unroll
        for (int j = 0; j < 8; j++) {
            int c = g * 8 + j;
            s += g_TQo2[c * 32 + k] * sMU[c];
        }
        sPb[g * 32 + k] = s;
    }
    __syncthreads();
    if (t < 32) {
        float s = 0.f;
#pragma unroll
        for (int g = 0; g < 8; g++) s += sPb[g * 32 + t];
        sB[t] = s;
    }
    __syncthreads();

    // GEMM 32(k) x 64(l) x 72: thread tile 4(k) x 2(l), packed over the l-pair
    int ko = (t >> 5) * 4, lo = (t & 31) * 2;
    unsigned long long pc[4];
#pragma unroll
    for (int i = 0; i < 4; i++) {
        float bi = sB[ko + i];
        pc[i] = pk2(bi, bi);
    }
#pragma unroll
    for (int c = 0; c < 8; c++) {
        float4 p = ld4(&sPo[c * 32 + ko]);
        unsigned long long h01 = pk2(sHmk[c * 64 + lo], sHmk[c * 64 + lo + 1]);
        unsigned long long q;
        q = pk2(p.x, p.x); FFMA2(pc[0], q, h01);
        q = pk2(p.y, p.y); FFMA2(pc[1], q, h01);
        q = pk2(p.z, p.z); FFMA2(pc[2], q, h01);
        q = pk2(p.w, p.w); FFMA2(pc[3], q, h01);
    }
#pragma unroll
    for (int c = 0; c < 64; c++) {
        float4 qv = ld4(&g_TQo[c * 32 + ko]);
        float2 a = ld2(&sAP[c * 64 + lo]);
        unsigned long long a01 = pk2(a.x, a.y);
        unsigned long long q;
        q = pk2(qv.x, qv.x); FFMA2(pc[0], q, a01);
        q = pk2(qv.y, qv.y); FFMA2(pc[1], q, a01);
        q = pk2(qv.z, qv.z); FFMA2(pc[2], q, a01);
        q = pk2(qv.w, qv.w); FFMA2(pc[3], q, a01);
    }
    float acc[4][2];
#pragma unroll
    for (int i = 0; i < 4; i++) upk2(pc[i], acc[i][0], acc[i][1]);

#pragma unroll
    for (int i = 0; i < 4; i++) {
        sV[(ko + i) * 65 + lo] = acc[i][0];
        sV[(ko + i) * 65 + lo + 1] = acc[i][1];
    }
    __syncthreads();

    {
        int k = t >> 3, j = t & 7;
        float ss = 0.f;
#pragma unroll
        for (int i = 0; i < 8; i++) {
            float x = sV[k * 65 + j * 8 + i];
            ss += x * x;
        }
        ss += __shfl_xor_sync(0xffffffffu, ss, 1);
        ss += __shfl_xor_sync(0xffffffffu, ss, 2);
        ss += __shfl_xor_sync(0xffffffffu, ss, 4);
        if (j == 0) sFac[k] = 8.f * rsqrtf(ss);
    }
    __syncthreads();

    const float4* v4 = reinterpret_cast<const float4*>(Vh) + (size_t)b * 2048;
    float4* o4 = reinterpret_cast<float4*>(out) + (size_t)b * 2048;
    float4 v[8];
#pragma unroll
    for (int j = 0; j < 8; j++) v[j] = v4[t + j * 256];
#pragma unroll
    for (int j = 0; j < 8; j++) {
        int i = t + j * 256;
        int l = i >> 5, k = i & 31;
        float pf = sV[k * 65 + l] * sFac[k];
        v[j].x *= pf; v[j].y *= pf; v[j].z *= pf; v[j].w *= pf;
        o4[i] = v[j];
    }
}

// ---------------- host ----------------
extern "C" void kernel_launch(void* const* d_in, const int* in_sizes, int n_in,
                              void* d_out, int out_size) {
    (void)in_sizes; (void)n_in; (void)out_size;
    const float* Hr = (const float*)d_in[0];
    const float* Hi = (const float*)d_in[1];
    const float* Vh = (const float*)d_in[2];
    const float* Qh = (const float*)d_in[3];
    const float* Ph = (const float*)d_in[4];
    const float* Qo = (const float*)d_in[5];
    const float* Po = (const float*)d_in[6];
    const float* gamma = (const float*)d_in[7];
    const float* beta = (const float*)d_in[8];

    static int attr_done = 0;
    if (!attr_done) {
        cudaFuncSetAttribute(k1_l0, cudaFuncAttributeMaxDynamicSharedMemorySize, (int)sizeof(SK1));
        cudaFuncSetAttribute(k2_full, cudaFuncAttributeMaxDynamicSharedMemorySize, (int)sizeof(SK2));
        attr_done = 1;
    }

    k0_prep<<<16, 256>>>(Qh, Ph, Qo, Po);
    k1_l0<<<1024, 256, sizeof(SK1)>>>(Hr, Hi, Ph);
    k2_full<<<1024, 256, sizeof(SK2)>>>(Ph, gamma, beta);
    k3_fused<<<1024, 256>>>(gamma, beta, Vh, (float*)d_out);
}